// round 1
// baseline (speedup 1.0000x reference)
#include <cuda_runtime.h>

// Shapes (fixed for this problem)
#define B_  2
#define T_  2048
#define H_  8
#define D_  64
#define M_  64
#define C_  64                 // chunk length (timesteps per block)
#define NC_ (T_ / C_)          // 32 chunks
#define ROWSTRIDE ((size_t)(H_ * D_))   // stride between consecutive t for fixed (b,h): 512 floats

// Scratch: per-(b,h,chunk) partial sums of fmap(k) over the chunk. [B,H,NC,D]
__device__ float g_chunksum[B_ * H_ * NC_ * D_];

__device__ __forceinline__ float fmap(float x) {
    // elu(x) + 1  (alpha = 1):  x>0 -> x+1 ; x<=0 -> exp(x)
    return x > 0.0f ? x + 1.0f : __expf(x);
}

// ---------------------------------------------------------------------------
// Kernel 1: per-chunk column sums of fmap(k).
// grid = B*H*NC blocks, 64 threads (one per d).
// ---------------------------------------------------------------------------
__global__ __launch_bounds__(64) void k_chunksum(const float* __restrict__ k) {
    const int bc = blockIdx.x;             // (b*H + h)*NC + c
    const int c  = bc % NC_;
    const int h  = (bc / NC_) % H_;
    const int b  = bc / (NC_ * H_);
    const int d  = threadIdx.x;

    const size_t base = (((size_t)b * T_ + (size_t)c * C_) * H_ + h) * D_;
    const float* kp = k + base + d;

    float s = 0.0f;
    #pragma unroll 8
    for (int t = 0; t < C_; t++) {
        s += fmap(kp[(size_t)t * ROWSTRIDE]);
    }
    g_chunksum[bc * D_ + d] = s;
}

// ---------------------------------------------------------------------------
// Kernel 2: main. grid = B*H*NC blocks, 256 threads (8 warps).
// Phase A: load fmap(k) tile [C][D] into smem.
// Phase B: threads 0..63 build carry from prior chunk sums, then run the
//          inclusive intra-chunk time-scan into ks_s.
// Phase C: warp w handles timesteps [w*8, w*8+8):
//            denom = qf . ksum          (warp butterfly reduce)
//            S     = qf . prefix_d(kf)  (Kogge-Stone warp scans + reduce)
//            out[t,m] = v[t,m] * S / denom
// ---------------------------------------------------------------------------
__global__ __launch_bounds__(256) void k_main(const float* __restrict__ q,
                                              const float* __restrict__ k,
                                              const float* __restrict__ v,
                                              float* __restrict__ out) {
    __shared__ float kf_s[C_][D_];   // fmap(k) tile
    __shared__ float ks_s[C_][D_];   // inclusive time-cumsum (incl. carry)

    const int bc = blockIdx.x;
    const int c  = bc % NC_;
    const int h  = (bc / NC_) % H_;
    const int b  = bc / (NC_ * H_);
    const int tid = threadIdx.x;

    const size_t base = (((size_t)b * T_ + (size_t)c * C_) * H_ + h) * D_;

    // Phase A: cooperative tile load (coalesced; consecutive tid -> consecutive d)
    for (int i = tid; i < C_ * D_; i += 256) {
        const int t = i >> 6;
        const int d = i & 63;
        kf_s[t][d] = fmap(k[base + (size_t)t * ROWSTRIDE + d]);
    }
    __syncthreads();

    // Phase B: carry + sequential intra-chunk scan (one thread per d lane)
    if (tid < D_) {
        const int d = tid;
        float run = 0.0f;
        const float* cs = &g_chunksum[((b * H_ + h) * NC_) * D_ + d];
        for (int cc = 0; cc < c; cc++) run += cs[cc * D_];
        #pragma unroll
        for (int t = 0; t < C_; t++) {
            run += kf_s[t][d];
            ks_s[t][d] = run;
        }
    }
    __syncthreads();

    // Phase C: per-timestep work, 8 rows per warp
    const int warp = tid >> 5;
    const int lane = tid & 31;

    #pragma unroll
    for (int r = 0; r < C_ / 8; r++) {
        const int t = warp * (C_ / 8) + r;
        const size_t rowoff = base + (size_t)t * ROWSTRIDE;

        const float q0 = fmap(q[rowoff + lane]);
        const float q1 = fmap(q[rowoff + lane + 32]);

        const float ks0 = ks_s[t][lane];
        const float ks1 = ks_s[t][lane + 32];
        float den = q0 * ks0 + q1 * ks1;

        const float kf0 = kf_s[t][lane];
        const float kf1 = kf_s[t][lane + 32];

        // inclusive scan of kf0 across the warp (d = 0..31)
        float p0 = kf0;
        #pragma unroll
        for (int o = 1; o < 32; o <<= 1) {
            float n = __shfl_up_sync(0xFFFFFFFFu, p0, o);
            if (lane >= o) p0 += n;
        }
        const float tot0 = __shfl_sync(0xFFFFFFFFu, p0, 31);

        // inclusive scan of kf1 (d = 32..63), offset by tot0
        float p1 = kf1;
        #pragma unroll
        for (int o = 1; o < 32; o <<= 1) {
            float n = __shfl_up_sync(0xFFFFFFFFu, p1, o);
            if (lane >= o) p1 += n;
        }

        float S = q0 * p0 + q1 * (tot0 + p1);

        // butterfly reduce both values -> all lanes hold the totals
        #pragma unroll
        for (int o = 16; o > 0; o >>= 1) {
            den += __shfl_xor_sync(0xFFFFFFFFu, den, o);
            S   += __shfl_xor_sync(0xFFFFFFFFu, S, o);
        }

        const float scale = S / den;
        out[rowoff + lane]      = v[rowoff + lane]      * scale;
        out[rowoff + lane + 32] = v[rowoff + lane + 32] * scale;
    }
}

extern "C" void kernel_launch(void* const* d_in, const int* in_sizes, int n_in,
                              void* d_out, int out_size) {
    const float* q = (const float*)d_in[0];
    const float* k = (const float*)d_in[1];
    const float* v = (const float*)d_in[2];
    float* out = (float*)d_out;

    const int nblocks = B_ * H_ * NC_;   // 512
    k_chunksum<<<nblocks, 64>>>(k);
    k_main<<<nblocks, 256>>>(q, k, v, out);
}

// round 2
// speedup vs baseline: 1.2576x; 1.2576x over previous
#include <cuda_runtime.h>

// Shapes (fixed for this problem)
#define B_  2
#define T_  2048
#define H_  8
#define D_  64
#define M_  64
#define C_  64                 // chunk length (timesteps per block)
#define NC_ (T_ / C_)          // 32 chunks
#define RS  512                // row stride in floats between consecutive t (H*D)
#define PAD 65                 // smem row stride (odd mod 32 -> conflict-free columns)

// Scratch: per-(b,h,chunk) partial sums of fmap(k) over the chunk. [B,H,NC,D]
__device__ float g_chunksum[B_ * H_ * NC_ * D_];

__device__ __forceinline__ float fmap(float x) {
    // elu(x) + 1 (alpha=1): x>0 -> x+1 ; x<=0 -> exp(x)
    return x > 0.0f ? x + 1.0f : __expf(x);
}

// ---------------------------------------------------------------------------
// Kernel 1: per-chunk column sums of fmap(k). grid = B*H*NC, 64 threads.
// ---------------------------------------------------------------------------
__global__ __launch_bounds__(64) void k_chunksum(const float* __restrict__ k) {
    const int bc = blockIdx.x;
    const int c  = bc % NC_;
    const int h  = (bc / NC_) % H_;
    const int b  = bc / (NC_ * H_);
    const int d  = threadIdx.x;

    const size_t base = (((size_t)b * T_ + (size_t)c * C_) * H_ + h) * D_;
    const float* kp = k + base + d;

    float s = 0.0f;
    #pragma unroll 8
    for (int t = 0; t < C_; t++) s += fmap(kp[(size_t)t * RS]);
    g_chunksum[bc * D_ + d] = s;
}

// ---------------------------------------------------------------------------
// Kernel 2: main. grid = B*H*NC blocks, 256 threads. Thread-per-timestep
// orientation in the compute phase: NO warp shuffles anywhere.
//
// smem layout (dynamic, ~56KB):
//   kf_s  [C][PAD]   fmap(k) tile
//   qf_s  [C][PAD]   fmap(q) tile
//   in_s  [C][PAD]   inclusive time-scan of kf (incl. cross-chunk carry)
//   segsum[4][64]    per-segment time sums
//   carr  [64]       cross-chunk carry per d
//   Sq,Dq,Kq,Qq [4][64]  per-d-quarter partials
//   scal  [64]       final per-timestep scale
// ---------------------------------------------------------------------------
__global__ __launch_bounds__(256) void k_main(const float* __restrict__ q,
                                              const float* __restrict__ k,
                                              const float* __restrict__ v,
                                              float* __restrict__ out) {
    extern __shared__ float sm[];
    float* kf_s   = sm;                    // C*PAD
    float* qf_s   = kf_s + C_ * PAD;       // C*PAD
    float* in_s   = qf_s + C_ * PAD;       // C*PAD
    float* segsum = in_s + C_ * PAD;       // 4*64
    float* carr   = segsum + 4 * 64;       // 64
    float* Sq     = carr + 64;             // 4*64
    float* Dq     = Sq + 256;              // 4*64
    float* Kq     = Dq + 256;              // 4*64
    float* Qq     = Kq + 256;              // 4*64
    float* scal   = Qq + 256;              // 64

    const int bc  = blockIdx.x;
    const int c   = bc % NC_;
    const int h   = (bc / NC_) % H_;
    const int b   = bc / (NC_ * H_);
    const int tid = threadIdx.x;

    const size_t base = (((size_t)b * T_ + (size_t)c * C_) * H_ + h) * D_;

    // ---- Phase A: vectorized coalesced load of k,q -> fmap -> smem ----
    // 1024 float4 rows-of-16 per tile; 4 iterations per thread.
    #pragma unroll
    for (int it = 0; it < 4; it++) {
        const int i  = tid + it * 256;         // 0..1023
        const int t  = i >> 4;                 // timestep
        const int dv = i & 15;                 // float4 index within row
        const size_t g = base + (size_t)t * RS + dv * 4;
        float4 kv = *(const float4*)(k + g);
        float4 qv = *(const float4*)(q + g);
        float* kd = &kf_s[t * PAD + dv * 4];
        float* qd = &qf_s[t * PAD + dv * 4];
        kd[0] = fmap(kv.x); kd[1] = fmap(kv.y); kd[2] = fmap(kv.z); kd[3] = fmap(kv.w);
        qd[0] = fmap(qv.x); qd[1] = fmap(qv.y); qd[2] = fmap(qv.z); qd[3] = fmap(qv.w);
    }

    // ---- cross-chunk carry per d (threads 0..63, gmem only, before sync) ----
    if (tid < D_) {
        float run = 0.0f;
        const float* cs = &g_chunksum[((b * H_ + h) * NC_) * D_ + tid];
        for (int cc = 0; cc < c; cc++) run += cs[cc * D_];
        carr[tid] = run;
    }
    __syncthreads();

    // ---- Phase B pass 1: local inclusive time-scan, 16 steps per thread ----
    {
        const int d = tid & 63, seg = tid >> 6;   // seg uniform per warp
        float run = 0.0f;
        #pragma unroll
        for (int i = 0; i < 16; i++) {
            const int t = seg * 16 + i;
            run += kf_s[t * PAD + d];
            in_s[t * PAD + d] = run;
        }
        segsum[seg * 64 + d] = run;
    }
    __syncthreads();

    // ---- Phase B pass 2: add carry + prior segment sums ----
    {
        const int d = tid & 63, seg = tid >> 6;
        float off = carr[d];
        for (int s = 0; s < seg; s++) off += segsum[s * 64 + d];
        #pragma unroll
        for (int i = 0; i < 16; i++) {
            const int t = seg * 16 + i;
            in_s[t * PAD + d] += off;
        }
    }
    __syncthreads();

    // ---- Phase C: thread (t = tid&63) handles d-quarter (dq = tid>>6) ----
    // dcum is a plain register accumulator: no shuffles.
    {
        const int t = tid & 63, dq = tid >> 6;
        float dcum = 0.0f, S = 0.0f, den = 0.0f, qs = 0.0f;
        #pragma unroll
        for (int j = 0; j < 16; j++) {
            const int d = dq * 16 + j;
            const float kf = kf_s[t * PAD + d];
            const float qf = qf_s[t * PAD + d];
            dcum += kf;
            S    += qf * dcum;
            den  += qf * in_s[t * PAD + d];
            qs   += qf;
        }
        Sq[dq * 64 + t] = S;
        Dq[dq * 64 + t] = den;
        Kq[dq * 64 + t] = dcum;
        Qq[dq * 64 + t] = qs;
    }
    __syncthreads();

    // ---- combine quarters: S = sum_q (S_q + ktot_{<q} * qsum_q) ----
    if (tid < C_) {
        const int t = tid;
        float kpre = 0.0f, S = 0.0f, den = 0.0f;
        #pragma unroll
        for (int qq = 0; qq < 4; qq++) {
            S    += Sq[qq * 64 + t] + kpre * Qq[qq * 64 + t];
            den  += Dq[qq * 64 + t];
            kpre += Kq[qq * 64 + t];
        }
        scal[t] = S / den;
    }
    __syncthreads();

    // ---- Phase D: vectorized coalesced output out = v * scale ----
    #pragma unroll
    for (int it = 0; it < 4; it++) {
        const int i  = tid + it * 256;
        const int t  = i >> 4;
        const int mv = i & 15;
        const size_t g = base + (size_t)t * RS + mv * 4;
        float4 vv = *(const float4*)(v + g);
        const float s = scal[t];
        vv.x *= s; vv.y *= s; vv.z *= s; vv.w *= s;
        *(float4*)(out + g) = vv;
    }
}

#define SMEM_BYTES ((3 * C_ * PAD + 4 * 64 + 64 + 4 * 256 + 64) * (int)sizeof(float))

extern "C" void kernel_launch(void* const* d_in, const int* in_sizes, int n_in,
                              void* d_out, int out_size) {
    const float* q = (const float*)d_in[0];
    const float* k = (const float*)d_in[1];
    const float* v = (const float*)d_in[2];
    float* out = (float*)d_out;

    // idempotent; needed because SMEM_BYTES (~56KB) exceeds the 48KB default
    cudaFuncSetAttribute(k_main, cudaFuncAttributeMaxDynamicSharedMemorySize, SMEM_BYTES);

    const int nblocks = B_ * H_ * NC_;   // 512
    k_chunksum<<<nblocks, 64>>>(k);
    k_main<<<nblocks, 256, SMEM_BYTES>>>(q, k, v, out);
}